// round 3
// baseline (speedup 1.0000x reference)
#include <cuda_runtime.h>
#include <math.h>

// ---------------- problem constants ----------------
#define BB    4
#define LP    768          // prefix length
#define LS    50           // suffix length
#define LTOT  818          // LP + LS
#define DD    2048
#define HH    8
#define HD    256
#define MV    8192
#define ME    4096
#define NTOK  (BB*LTOT)    // 3272
#define SCALE_ 0.0625f     // HD^-0.5

// ---------------- scratch (device globals, allocation-free) ----------------
__device__ float g_n  [NTOK*DD];      // rmsnorm output
__device__ float g_q  [NTOK*DD];      // q (B,L,H*HD)
__device__ float g_kb [NTOK*HD];      // k (B,L,HD)  (KV=1)
__device__ float g_vb [NTOK*HD];      // v
__device__ float g_att[NTOK*DD];      // attention output (B,L,H*HD)
__device__ float g_mlp[NTOK*MV];      // gate / act scratch (ld = 8192)

// ---------------- helpers ----------------
__device__ __forceinline__ long rowmap(int r, int seg_len, int seg_off) {
    int b = r / seg_len;
    return (long)b * LTOT + seg_off + (r - b * seg_len);
}

__device__ __forceinline__ float gelu_tanh(float x) {
    float t = tanhf(0.7978845608028654f * (x + 0.044715f * x * x * x));
    return 0.5f * x * (1.0f + t);
}

// ---------------- init: copy prefix/suffix into h (=d_out) ----------------
__global__ void init_h_kernel(const float* __restrict__ prefix,
                              const float* __restrict__ suffix,
                              float* __restrict__ h) {
    int tok = blockIdx.x;
    int b = tok / LTOT, t = tok - b * LTOT;
    const float* src = (t < LP) ? prefix + ((size_t)(b * LP + t)) * DD
                                : suffix + ((size_t)(b * LS + (t - LP))) * DD;
    const float4* s4 = (const float4*)src;
    float4* dst = (float4*)(h + (size_t)tok * DD);
    dst[threadIdx.x]       = s4[threadIdx.x];
    dst[threadIdx.x + 256] = s4[threadIdx.x + 256];
}

// ---------------- rmsnorm ----------------
__global__ void rmsnorm_kernel(const float* __restrict__ x, float* __restrict__ out,
                               const float* __restrict__ wp, const float* __restrict__ we) {
    int tok = blockIdx.x;
    int t = tok % LTOT;
    const float* w = (t < LP) ? wp : we;
    const float4* xv = (const float4*)(x + (size_t)tok * DD);
    float4 v0 = xv[threadIdx.x];
    float4 v1 = xv[threadIdx.x + 256];
    float ss = v0.x*v0.x + v0.y*v0.y + v0.z*v0.z + v0.w*v0.w
             + v1.x*v1.x + v1.y*v1.y + v1.z*v1.z + v1.w*v1.w;
    __shared__ float red[8];
    #pragma unroll
    for (int o = 16; o; o >>= 1) ss += __shfl_xor_sync(0xffffffffu, ss, o);
    if ((threadIdx.x & 31) == 0) red[threadIdx.x >> 5] = ss;
    __syncthreads();
    float tot = red[0]+red[1]+red[2]+red[3]+red[4]+red[5]+red[6]+red[7];
    float sc = rsqrtf(tot * (1.0f / DD) + 1e-6f);
    const float4* wv = (const float4*)w;
    float4 w0 = wv[threadIdx.x];
    float4 w1 = wv[threadIdx.x + 256];
    float4 o0, o1;
    o0.x = v0.x*sc*(1.f+w0.x); o0.y = v0.y*sc*(1.f+w0.y);
    o0.z = v0.z*sc*(1.f+w0.z); o0.w = v0.w*sc*(1.f+w0.w);
    o1.x = v1.x*sc*(1.f+w1.x); o1.y = v1.y*sc*(1.f+w1.y);
    o1.z = v1.z*sc*(1.f+w1.z); o1.w = v1.w*sc*(1.f+w1.w);
    float4* ov = (float4*)(out + (size_t)tok * DD);
    ov[threadIdx.x]       = o0;
    ov[threadIdx.x + 256] = o1;
}

// ---------------- RoPE (in-place on q and k) ----------------
__global__ void rope_kernel(float* __restrict__ q, float* __restrict__ k) {
    int tok = blockIdx.x;
    int pos = tok % LTOT;
    for (int idx = threadIdx.x; idx < 9 * 128; idx += 256) {
        int head = idx >> 7, i = idx & 127;
        // inv = 1 / 10000^(i/128)
        float inv = expf(-(float)i * (9.210340371976184f / 128.0f));
        float ang = (float)pos * inv;
        float c = cosf(ang), s = sinf(ang);
        float* base = (head < HH) ? (q + (size_t)tok * DD + head * HD)
                                  : (k + (size_t)tok * HD);
        float x0 = base[i], x1 = base[i + 128];
        base[i]       = x0 * c - x1 * s;
        base[i + 128] = x1 * c + x0 * s;
    }
}

// ---------------- attention ----------------
// grid (26, 8, 4): 32-query tile per block, 256 threads.
// smem: Q[32][257] + KV-chunk[32][260] + scores[32][824]
#define QS_LD 257
#define KS_LD 260
#define SC_LD 824
#define ATTN_SMEM ((32*QS_LD + 32*KS_LD + 32*SC_LD) * 4)

__global__ void __launch_bounds__(256) attn_kernel(const float* __restrict__ q,
                                                   const float* __restrict__ k,
                                                   const float* __restrict__ v,
                                                   float* __restrict__ att) {
    extern __shared__ float sm[];
    float* qs = sm;
    float* ks = qs + 32 * QS_LD;
    float* sc = ks + 32 * KS_LD;
    int b = blockIdx.z, h = blockIdx.y, qt = blockIdx.x;
    int t = threadIdx.x;
    int q0 = qt * 32;

    // load Q tile
    for (int i = t; i < 32 * 256; i += 256) {
        int qi = i >> 8, d = i & 255;
        int qg = q0 + qi;
        qs[qi * QS_LD + d] = (qg < LTOT)
            ? q[((size_t)(b * LTOT + qg)) * DD + h * HD + d] : 0.0f;
    }
    __syncthreads();

    const int nchunk = (LTOT + 31) / 32;   // 26
    int qi0 = (t & 15) * 2, kj0 = (t >> 4) * 2;

    // ---- scores ----
    for (int kc = 0; kc < nchunk; kc++) {
        int kbase = kc * 32;
        for (int i = t; i < 32 * 64; i += 256) {
            int kj = i >> 6, c4 = i & 63;
            int kg = kbase + kj;
            float4 vv = (kg < LTOT)
                ? *(const float4*)(k + ((size_t)(b * LTOT + kg)) * HD + c4 * 4)
                : make_float4(0.f, 0.f, 0.f, 0.f);
            *(float4*)(ks + kj * KS_LD + c4 * 4) = vv;
        }
        __syncthreads();

        float s00 = 0.f, s01 = 0.f, s10 = 0.f, s11 = 0.f;
        const float* qa = qs + qi0 * QS_LD;
        const float* qb = qa + QS_LD;
        const float* ka = ks + kj0 * KS_LD;
        const float* kb = ka + KS_LD;
        #pragma unroll 8
        for (int d = 0; d < 256; d++) {
            float a0 = qa[d], a1 = qb[d], c0 = ka[d], c1 = kb[d];
            s00 += a0 * c0; s01 += a0 * c1;
            s10 += a1 * c0; s11 += a1 * c1;
        }
        int qg0 = q0 + qi0, qg1 = qg0 + 1;
        int kg0 = kbase + kj0, kg1 = kg0 + 1;
        if (kg0 < LTOT) {
            sc[qi0 * SC_LD + kg0]       = ((kg0 < LP) || (kg0 <= qg0)) ? s00 * SCALE_ : -1e30f;
            sc[(qi0 + 1) * SC_LD + kg0] = ((kg0 < LP) || (kg0 <= qg1)) ? s10 * SCALE_ : -1e30f;
        }
        if (kg1 < LTOT) {
            sc[qi0 * SC_LD + kg1]       = ((kg1 < LP) || (kg1 <= qg0)) ? s01 * SCALE_ : -1e30f;
            sc[(qi0 + 1) * SC_LD + kg1] = ((kg1 < LP) || (kg1 <= qg1)) ? s11 * SCALE_ : -1e30f;
        }
        __syncthreads();
    }

    // ---- softmax: warp w handles rows w*4 .. w*4+3 ----
    {
        int w = t >> 5, lane = t & 31;
        for (int j = 0; j < 4; j++) {
            float* row = sc + (w * 4 + j) * SC_LD;
            float mx = -1e30f;
            for (int kk = lane; kk < LTOT; kk += 32) mx = fmaxf(mx, row[kk]);
            #pragma unroll
            for (int o = 16; o; o >>= 1) mx = fmaxf(mx, __shfl_xor_sync(0xffffffffu, mx, o));
            float sum = 0.f;
            for (int kk = lane; kk < LTOT; kk += 32) {
                float e = expf(row[kk] - mx);
                row[kk] = e;
                sum += e;
            }
            #pragma unroll
            for (int o = 16; o; o >>= 1) sum += __shfl_xor_sync(0xffffffffu, sum, o);
            float invs = 1.0f / sum;
            for (int kk = lane; kk < LTOT; kk += 32) row[kk] *= invs;
        }
    }
    __syncthreads();

    // ---- P @ V ----
    int qi = t >> 3, dbase = t & 7;
    float o[32];
    #pragma unroll
    for (int j = 0; j < 32; j++) o[j] = 0.f;
    for (int kc = 0; kc < nchunk; kc++) {
        int kbase = kc * 32;
        for (int i = t; i < 32 * 64; i += 256) {
            int kj = i >> 6, c4 = i & 63;
            int kg = kbase + kj;
            float4 vv = (kg < LTOT)
                ? *(const float4*)(v + ((size_t)(b * LTOT + kg)) * HD + c4 * 4)
                : make_float4(0.f, 0.f, 0.f, 0.f);
            *(float4*)(ks + kj * KS_LD + c4 * 4) = vv;
        }
        __syncthreads();
        int kmax = min(32, LTOT - kbase);
        for (int kj = 0; kj < kmax; kj++) {
            float p = sc[qi * SC_LD + kbase + kj];
            const float* vr = ks + kj * KS_LD + dbase;
            #pragma unroll
            for (int j = 0; j < 32; j++) o[j] += p * vr[8 * j];
        }
        __syncthreads();
    }
    int qg = q0 + qi;
    if (qg < LTOT) {
        float* dst = att + ((size_t)(b * LTOT + qg)) * DD + h * HD + dbase;
        #pragma unroll
        for (int j = 0; j < 32; j++) dst[8 * j] = o[j];
    }
}

// ---------------- generic token-mapped SGEMM: C = A(tok rows) @ B ----------------
// BM=BN=128, BK=16, 256 threads, 8x8 per thread.
// EPI 0: C = acc; EPI 1: C += acc (residual); EPI 2: C = gelu(G)*acc
template <int EPI>
__global__ void __launch_bounds__(256, 2) gemm_tok(const float* __restrict__ A,
                                                   const float* __restrict__ Bm,
                                                   float* __restrict__ C,
                                                   const float* __restrict__ G,
                                                   int M, int N, int K,
                                                   int lda, int ldc,
                                                   int seg_len, int seg_off) {
    __shared__ float sA[16 * 128];
    __shared__ float sB[16 * 128];
    int t = threadIdx.x;
    int m0 = blockIdx.y * 128, n0 = blockIdx.x * 128;
    int tx = t & 15, ty = t >> 4;

    float acc[8][8];
    #pragma unroll
    for (int i = 0; i < 8; i++)
        #pragma unroll
        for (int j = 0; j < 8; j++) acc[i][j] = 0.f;

    // A-load geometry: ids t, t+256 -> (row, 4-float col group)
    int arow0 = t >> 2,          ac0 = (t & 3) * 4;
    int arow1 = (t + 256) >> 2,  ac1 = ((t + 256) & 3) * 4;
    int r0 = m0 + arow0, r1 = m0 + arow1;
    long offA0 = (r0 < M) ? rowmap(r0, seg_len, seg_off) * (long)lda : -1;
    long offA1 = (r1 < M) ? rowmap(r1, seg_len, seg_off) * (long)lda : -1;
    // B-load geometry
    int brow0 = t >> 5, brow1 = brow0 + 8;
    int bc = (t & 31) * 4;

    for (int k0 = 0; k0 < K; k0 += 16) {
        float4 va0 = (offA0 >= 0) ? *(const float4*)(A + offA0 + k0 + ac0)
                                  : make_float4(0.f, 0.f, 0.f, 0.f);
        float4 va1 = (offA1 >= 0) ? *(const float4*)(A + offA1 + k0 + ac1)
                                  : make_float4(0.f, 0.f, 0.f, 0.f);
        float4 vb0 = *(const float4*)(Bm + (size_t)(k0 + brow0) * N + n0 + bc);
        float4 vb1 = *(const float4*)(Bm + (size_t)(k0 + brow1) * N + n0 + bc);
        __syncthreads();
        sA[(ac0 + 0) * 128 + arow0] = va0.x;
        sA[(ac0 + 1) * 128 + arow0] = va0.y;
        sA[(ac0 + 2) * 128 + arow0] = va0.z;
        sA[(ac0 + 3) * 128 + arow0] = va0.w;
        sA[(ac1 + 0) * 128 + arow1] = va1.x;
        sA[(ac1 + 1) * 128 + arow1] = va1.y;
        sA[(ac1 + 2) * 128 + arow1] = va1.z;
        sA[(ac1 + 3) * 128 + arow1] = va1.w;
        *(float4*)(sB + brow0 * 128 + bc) = vb0;
        *(float4*)(sB + brow1 * 128 + bc) = vb1;
        __syncthreads();

        #pragma unroll
        for (int kk = 0; kk < 16; kk++) {
            float4 a0 = *(const float4*)(sA + kk * 128 + ty * 8);
            float4 a1 = *(const float4*)(sA + kk * 128 + ty * 8 + 4);
            float4 b0 = *(const float4*)(sB + kk * 128 + tx * 8);
            float4 b1 = *(const float4*)(sB + kk * 128 + tx * 8 + 4);
            float ar[8] = {a0.x, a0.y, a0.z, a0.w, a1.x, a1.y, a1.z, a1.w};
            float br[8] = {b0.x, b0.y, b0.z, b0.w, b1.x, b1.y, b1.z, b1.w};
            #pragma unroll
            for (int i = 0; i < 8; i++)
                #pragma unroll
                for (int j = 0; j < 8; j++)
                    acc[i][j] += ar[i] * br[j];
        }
    }

    #pragma unroll
    for (int i = 0; i < 8; i++) {
        int r = m0 + ty * 8 + i;
        if (r >= M) continue;
        long base = rowmap(r, seg_len, seg_off) * (long)ldc + n0 + tx * 8;
        #pragma unroll
        for (int j = 0; j < 8; j++) {
            float val = acc[i][j];
            if (EPI == 1) val += C[base + j];
            if (EPI == 2) val = gelu_tanh(G[base + j]) * val;
            C[base + j] = val;
        }
    }
}

// ---------------- host-side launch helpers ----------------
static void launch_gemm(int epi, const float* A, const float* Bm, float* C, const float* G,
                        int M, int N, int K, int lda, int ldc, int seg_len, int seg_off) {
    dim3 grid(N / 128, (M + 127) / 128);
    if (epi == 0)      gemm_tok<0><<<grid, 256>>>(A, Bm, C, G, M, N, K, lda, ldc, seg_len, seg_off);
    else if (epi == 1) gemm_tok<1><<<grid, 256>>>(A, Bm, C, G, M, N, K, lda, ldc, seg_len, seg_off);
    else               gemm_tok<2><<<grid, 256>>>(A, Bm, C, G, M, N, K, lda, ldc, seg_len, seg_off);
}

extern "C" void kernel_launch(void* const* d_in, const int* in_sizes, int n_in,
                              void* d_out, int out_size) {
    const float* prefix = (const float*)d_in[0];
    const float* suffix = (const float*)d_in[1];
    // d_in[2] = attention_mask (analytic: k<768 || k<=q), d_in[3] = position_ids (arange) — unused
    const float* p_ln1  = (const float*)d_in[4];
    const float* p_q    = (const float*)d_in[5];
    const float* p_k    = (const float*)d_in[6];
    const float* p_v    = (const float*)d_in[7];
    const float* p_o    = (const float*)d_in[8];
    const float* p_ln2  = (const float*)d_in[9];
    const float* p_gate = (const float*)d_in[10];
    const float* p_up   = (const float*)d_in[11];
    const float* p_down = (const float*)d_in[12];
    const float* e_ln1  = (const float*)d_in[13];
    const float* e_q    = (const float*)d_in[14];
    const float* e_k    = (const float*)d_in[15];
    const float* e_v    = (const float*)d_in[16];
    const float* e_o    = (const float*)d_in[17];
    const float* e_ln2  = (const float*)d_in[18];
    const float* e_gate = (const float*)d_in[19];
    const float* e_up   = (const float*)d_in[20];
    const float* e_down = (const float*)d_in[21];

    float* h = (float*)d_out;
    float *n_, *q_, *k_, *v_, *att_, *mlp_;
    cudaGetSymbolAddress((void**)&n_,   g_n);
    cudaGetSymbolAddress((void**)&q_,   g_q);
    cudaGetSymbolAddress((void**)&k_,   g_kb);
    cudaGetSymbolAddress((void**)&v_,   g_vb);
    cudaGetSymbolAddress((void**)&att_, g_att);
    cudaGetSymbolAddress((void**)&mlp_, g_mlp);

    cudaFuncSetAttribute(attn_kernel, cudaFuncAttributeMaxDynamicSharedMemorySize, ATTN_SMEM);

    init_h_kernel<<<NTOK, 256>>>(prefix, suffix, h);

    for (int layer = 0; layer < 2; layer++) {
        size_t lW  = (size_t)layer * DD * DD;      // 2048x2048 weights
        size_t lKV = (size_t)layer * DD * HD;      // 2048x256
        size_t lGp = (size_t)layer * DD * MV;      // 2048x8192
        size_t lGe = (size_t)layer * DD * ME;      // 2048x4096
        size_t lDp = (size_t)layer * MV * DD;      // 8192x2048
        size_t lDe = (size_t)layer * ME * DD;      // 4096x2048

        // ln1
        rmsnorm_kernel<<<NTOK, 256>>>(h, n_, p_ln1 + layer * DD, e_ln1 + layer * DD);
        // qkv (prefix / suffix)
        launch_gemm(0, n_, p_q + lW,  q_, nullptr, BB*LP, DD,  DD, DD, DD, LP, 0);
        launch_gemm(0, n_, p_k + lKV, k_, nullptr, BB*LP, HD,  DD, DD, HD, LP, 0);
        launch_gemm(0, n_, p_v + lKV, v_, nullptr, BB*LP, HD,  DD, DD, HD, LP, 0);
        launch_gemm(0, n_, e_q + lW,  q_, nullptr, BB*LS, DD,  DD, DD, DD, LS, LP);
        launch_gemm(0, n_, e_k + lKV, k_, nullptr, BB*LS, HD,  DD, DD, HD, LS, LP);
        launch_gemm(0, n_, e_v + lKV, v_, nullptr, BB*LS, HD,  DD, DD, HD, LS, LP);
        // rope
        rope_kernel<<<NTOK, 256>>>(q_, k_);
        // attention
        dim3 ag((LTOT + 31) / 32, HH, BB);
        attn_kernel<<<ag, 256, ATTN_SMEM>>>(q_, k_, v_, att_);
        // o-proj + residual (into h)
        launch_gemm(1, att_, p_o + lW, h, nullptr, BB*LP, DD, DD, DD, DD, LP, 0);
        launch_gemm(1, att_, e_o + lW, h, nullptr, BB*LS, DD, DD, DD, DD, LS, LP);
        // ln2
        rmsnorm_kernel<<<NTOK, 256>>>(h, n_, p_ln2 + layer * DD, e_ln2 + layer * DD);
        // gate
        launch_gemm(0, n_, p_gate + lGp, mlp_, nullptr, BB*LP, MV, DD, DD, MV, LP, 0);
        launch_gemm(0, n_, e_gate + lGe, mlp_, nullptr, BB*LS, ME, DD, DD, MV, LS, LP);
        // up with fused act = gelu(gate) * up  (reads/writes g_mlp in place)
        launch_gemm(2, n_, p_up + lGp, mlp_, mlp_, BB*LP, MV, DD, DD, MV, LP, 0);
        launch_gemm(2, n_, e_up + lGe, mlp_, mlp_, BB*LS, ME, DD, DD, MV, LS, LP);
        // down + residual (into h)
        launch_gemm(1, mlp_, p_down + lDp, h, nullptr, BB*LP, DD, MV, MV, DD, LP, 0);
        launch_gemm(1, mlp_, e_down + lDe, h, nullptr, BB*LS, DD, ME, MV, DD, LS, LP);
    }
}

// round 4
// speedup vs baseline: 2.7579x; 2.7579x over previous
#include <cuda_runtime.h>
#include <math.h>
#include <stdint.h>

// ---------------- problem constants ----------------
#define BB    4
#define LP    768
#define LS    50
#define LTOT  818
#define DD    2048
#define HH    8
#define HD    256
#define MV    8192
#define ME    4096
#define NTOK  (BB*LTOT)
#define SCALE_ 0.0625f

// ---------------- scratch ----------------
__device__ float g_n  [NTOK*DD];
__device__ float g_q  [NTOK*DD];
__device__ float g_kb [NTOK*HD];
__device__ float g_vb [NTOK*HD];
__device__ float g_att[NTOK*DD];
__device__ float g_mlp[(size_t)NTOK*MV];
__device__ float g_wtf[188743680ull];   // tf32-rounded weights (755MB)

// ---------------- helpers ----------------
__device__ __forceinline__ long rowmap(int r, int seg_len, int seg_off) {
    int b = r / seg_len;
    return (long)b * LTOT + seg_off + (r - b * seg_len);
}
__device__ __forceinline__ float gelu_tanh(float x) {
    float t = tanhf(0.7978845608028654f * (x + 0.044715f * x * x * x));
    return 0.5f * x * (1.0f + t);
}
__device__ __forceinline__ float tf32r(float x) {
    uint32_t u;
    asm("cvt.rna.tf32.f32 %0, %1;" : "=r"(u) : "f"(x));
    return __uint_as_float(u);
}
__device__ __forceinline__ void cpa16(uint32_t dst, const void* src, int sz) {
    asm volatile("cp.async.ca.shared.global [%0], [%1], 16, %2;\n"
                 :: "r"(dst), "l"(src), "r"(sz));
}
#define CP_COMMIT() asm volatile("cp.async.commit_group;\n")
#define CP_WAIT1()  asm volatile("cp.async.wait_group 1;\n")
#define CP_WAIT0()  asm volatile("cp.async.wait_group 0;\n")

__device__ __forceinline__ void mma_tf32(float* c, const uint32_t* a, const uint32_t* b) {
    asm volatile("mma.sync.aligned.m16n8k8.row.col.f32.tf32.tf32.f32 "
                 "{%0,%1,%2,%3}, {%4,%5,%6,%7}, {%8,%9}, {%0,%1,%2,%3};\n"
                 : "+f"(c[0]), "+f"(c[1]), "+f"(c[2]), "+f"(c[3])
                 : "r"(a[0]), "r"(a[1]), "r"(a[2]), "r"(a[3]),
                   "r"(b[0]), "r"(b[1]));
}

// ---------------- weight tf32 rounding ----------------
__global__ void round_w(const float4* __restrict__ s, float4* __restrict__ d, int n4) {
    for (int i = blockIdx.x * blockDim.x + threadIdx.x; i < n4; i += gridDim.x * blockDim.x) {
        float4 v = s[i];
        v.x = tf32r(v.x); v.y = tf32r(v.y); v.z = tf32r(v.z); v.w = tf32r(v.w);
        d[i] = v;
    }
}

// ---------------- init: copy prefix/suffix into h (=d_out) ----------------
__global__ void init_h_kernel(const float* __restrict__ prefix,
                              const float* __restrict__ suffix,
                              float* __restrict__ h) {
    int tok = blockIdx.x;
    int b = tok / LTOT, t = tok - b * LTOT;
    const float* src = (t < LP) ? prefix + ((size_t)(b * LP + t)) * DD
                                : suffix + ((size_t)(b * LS + (t - LP))) * DD;
    const float4* s4 = (const float4*)src;
    float4* dst = (float4*)(h + (size_t)tok * DD);
    dst[threadIdx.x]       = s4[threadIdx.x];
    dst[threadIdx.x + 256] = s4[threadIdx.x + 256];
}

// ---------------- rmsnorm (output tf32-rounded: feeds GEMMs only) ----------------
__global__ void rmsnorm_kernel(const float* __restrict__ x, float* __restrict__ out,
                               const float* __restrict__ wp, const float* __restrict__ we) {
    int tok = blockIdx.x;
    int t = tok % LTOT;
    const float* w = (t < LP) ? wp : we;
    const float4* xv = (const float4*)(x + (size_t)tok * DD);
    float4 v0 = xv[threadIdx.x];
    float4 v1 = xv[threadIdx.x + 256];
    float ss = v0.x*v0.x + v0.y*v0.y + v0.z*v0.z + v0.w*v0.w
             + v1.x*v1.x + v1.y*v1.y + v1.z*v1.z + v1.w*v1.w;
    __shared__ float red[8];
    #pragma unroll
    for (int o = 16; o; o >>= 1) ss += __shfl_xor_sync(0xffffffffu, ss, o);
    if ((threadIdx.x & 31) == 0) red[threadIdx.x >> 5] = ss;
    __syncthreads();
    float tot = red[0]+red[1]+red[2]+red[3]+red[4]+red[5]+red[6]+red[7];
    float sc = rsqrtf(tot * (1.0f / DD) + 1e-6f);
    const float4* wv = (const float4*)w;
    float4 w0 = wv[threadIdx.x];
    float4 w1 = wv[threadIdx.x + 256];
    float4 o0, o1;
    o0.x = tf32r(v0.x*sc*(1.f+w0.x)); o0.y = tf32r(v0.y*sc*(1.f+w0.y));
    o0.z = tf32r(v0.z*sc*(1.f+w0.z)); o0.w = tf32r(v0.w*sc*(1.f+w0.w));
    o1.x = tf32r(v1.x*sc*(1.f+w1.x)); o1.y = tf32r(v1.y*sc*(1.f+w1.y));
    o1.z = tf32r(v1.z*sc*(1.f+w1.z)); o1.w = tf32r(v1.w*sc*(1.f+w1.w));
    float4* ov = (float4*)(out + (size_t)tok * DD);
    ov[threadIdx.x]       = o0;
    ov[threadIdx.x + 256] = o1;
}

// ---------------- RoPE ----------------
__global__ void rope_kernel(float* __restrict__ q, float* __restrict__ k) {
    int tok = blockIdx.x;
    int pos = tok % LTOT;
    for (int idx = threadIdx.x; idx < 9 * 128; idx += 256) {
        int head = idx >> 7, i = idx & 127;
        float inv = expf(-(float)i * (9.210340371976184f / 128.0f));
        float ang = (float)pos * inv;
        float c = cosf(ang), s = sinf(ang);
        float* base = (head < HH) ? (q + (size_t)tok * DD + head * HD)
                                  : (k + (size_t)tok * HD);
        float x0 = base[i], x1 = base[i + 128];
        base[i]       = x0 * c - x1 * s;
        base[i + 128] = x1 * c + x0 * s;
    }
}

// ---------------- attention (fp32; output tf32-rounded: feeds o-proj GEMM) ----------------
#define QS_LD 257
#define KS_LD 260
#define SC_LD 824
#define ATTN_SMEM ((32*QS_LD + 32*KS_LD + 32*SC_LD) * 4)

__global__ void __launch_bounds__(256) attn_kernel(const float* __restrict__ q,
                                                   const float* __restrict__ k,
                                                   const float* __restrict__ v,
                                                   float* __restrict__ att) {
    extern __shared__ float sm[];
    float* qs = sm;
    float* ks = qs + 32 * QS_LD;
    float* sc = ks + 32 * KS_LD;
    int b = blockIdx.z, h = blockIdx.y, qt = blockIdx.x;
    int t = threadIdx.x;
    int q0 = qt * 32;

    for (int i = t; i < 32 * 256; i += 256) {
        int qi = i >> 8, d = i & 255;
        int qg = q0 + qi;
        qs[qi * QS_LD + d] = (qg < LTOT)
            ? q[((size_t)(b * LTOT + qg)) * DD + h * HD + d] : 0.0f;
    }
    __syncthreads();

    const int nchunk = (LTOT + 31) / 32;
    int qi0 = (t & 15) * 2, kj0 = (t >> 4) * 2;

    for (int kc = 0; kc < nchunk; kc++) {
        int kbase = kc * 32;
        for (int i = t; i < 32 * 64; i += 256) {
            int kj = i >> 6, c4 = i & 63;
            int kg = kbase + kj;
            float4 vv = (kg < LTOT)
                ? *(const float4*)(k + ((size_t)(b * LTOT + kg)) * HD + c4 * 4)
                : make_float4(0.f, 0.f, 0.f, 0.f);
            *(float4*)(ks + kj * KS_LD + c4 * 4) = vv;
        }
        __syncthreads();

        float s00 = 0.f, s01 = 0.f, s10 = 0.f, s11 = 0.f;
        const float* qa = qs + qi0 * QS_LD;
        const float* qb = qa + QS_LD;
        const float* ka = ks + kj0 * KS_LD;
        const float* kb = ka + KS_LD;
        #pragma unroll 8
        for (int d = 0; d < 256; d++) {
            float a0 = qa[d], a1 = qb[d], c0 = ka[d], c1 = kb[d];
            s00 += a0 * c0; s01 += a0 * c1;
            s10 += a1 * c0; s11 += a1 * c1;
        }
        int qg0 = q0 + qi0, qg1 = qg0 + 1;
        int kg0 = kbase + kj0, kg1 = kg0 + 1;
        if (kg0 < LTOT) {
            sc[qi0 * SC_LD + kg0]       = ((kg0 < LP) || (kg0 <= qg0)) ? s00 * SCALE_ : -1e30f;
            sc[(qi0 + 1) * SC_LD + kg0] = ((kg0 < LP) || (kg0 <= qg1)) ? s10 * SCALE_ : -1e30f;
        }
        if (kg1 < LTOT) {
            sc[qi0 * SC_LD + kg1]       = ((kg1 < LP) || (kg1 <= qg0)) ? s01 * SCALE_ : -1e30f;
            sc[(qi0 + 1) * SC_LD + kg1] = ((kg1 < LP) || (kg1 <= qg1)) ? s11 * SCALE_ : -1e30f;
        }
        __syncthreads();
    }

    {
        int w = t >> 5, lane = t & 31;
        for (int j = 0; j < 4; j++) {
            float* row = sc + (w * 4 + j) * SC_LD;
            float mx = -1e30f;
            for (int kk = lane; kk < LTOT; kk += 32) mx = fmaxf(mx, row[kk]);
            #pragma unroll
            for (int o = 16; o; o >>= 1) mx = fmaxf(mx, __shfl_xor_sync(0xffffffffu, mx, o));
            float sum = 0.f;
            for (int kk = lane; kk < LTOT; kk += 32) {
                float e = expf(row[kk] - mx);
                row[kk] = e;
                sum += e;
            }
            #pragma unroll
            for (int o = 16; o; o >>= 1) sum += __shfl_xor_sync(0xffffffffu, sum, o);
            float invs = 1.0f / sum;
            for (int kk = lane; kk < LTOT; kk += 32) row[kk] *= invs;
        }
    }
    __syncthreads();

    int qi = t >> 3, dbase = t & 7;
    float o[32];
    #pragma unroll
    for (int j = 0; j < 32; j++) o[j] = 0.f;
    for (int kc = 0; kc < nchunk; kc++) {
        int kbase = kc * 32;
        for (int i = t; i < 32 * 64; i += 256) {
            int kj = i >> 6, c4 = i & 63;
            int kg = kbase + kj;
            float4 vv = (kg < LTOT)
                ? *(const float4*)(v + ((size_t)(b * LTOT + kg)) * HD + c4 * 4)
                : make_float4(0.f, 0.f, 0.f, 0.f);
            *(float4*)(ks + kj * KS_LD + c4 * 4) = vv;
        }
        __syncthreads();
        int kmax = min(32, LTOT - kbase);
        for (int kj = 0; kj < kmax; kj++) {
            float p = sc[qi * SC_LD + kbase + kj];
            const float* vr = ks + kj * KS_LD + dbase;
            #pragma unroll
            for (int j = 0; j < 32; j++) o[j] += p * vr[8 * j];
        }
        __syncthreads();
    }
    int qg = q0 + qi;
    if (qg < LTOT) {
        float* dst = att + ((size_t)(b * LTOT + qg)) * DD + h * HD + dbase;
        #pragma unroll
        for (int j = 0; j < 32; j++) dst[8 * j] = tf32r(o[j]);
    }
}

// ---------------- TF32 tensor-core GEMM ----------------
// BM=128, BN=128, BK=32, 256 threads, 8 warps (2m x 4n), warp tile 64x32.
// Inputs (A and Bm) are already tf32-rounded fp32 values -> raw cp.async staging.
// EPI 0: C = acc; 1: C += acc; 2: C = tf32(gelu(G)*acc)
#define SA_SZ (128*36)
#define SB_SZ (32*136)
#define STG   (SA_SZ + SB_SZ)
#define GEMM_SMEM (2*STG*4)

template <int EPI>
__global__ void __launch_bounds__(256, 2)
gemm_tc(const float* __restrict__ A,
        const float* __restrict__ B0, float* __restrict__ C0,
        const float* __restrict__ B1, float* __restrict__ C1,
        const float* __restrict__ G,
        int M, int N, int K, int lda, int ldc, int seg_len, int seg_off) {
    extern __shared__ float smf[];
    const float* Bm = blockIdx.z ? B1 : B0;
    float* C = blockIdx.z ? C1 : C0;

    int t = threadIdx.x;
    int m0 = blockIdx.y * 128, n0 = blockIdx.x * 128;
    uint32_t smb = (uint32_t)__cvta_generic_to_shared(smf);

    // staging geometry
    int am = t >> 3;             // A row within tile (+32*i)
    int ak = (t & 7) * 4;        // A k-group
    int bk = t >> 5;             // B k-row (+8*i)
    int bn = (t & 31) * 4;       // B n-group
    long offA[4]; int szA[4];
    #pragma unroll
    for (int i = 0; i < 4; i++) {
        int r = m0 + am + 32 * i;
        bool vld = r < M;
        offA[i] = vld ? rowmap(r, seg_len, seg_off) * (long)lda : 0;
        szA[i] = vld ? 16 : 0;
    }

    int warp = t >> 5, lane = t & 31;
    int wm = warp >> 2, wn = warp & 3;
    int lr = lane >> 2, lc = lane & 3;

    float acc[4][4][4];
    #pragma unroll
    for (int mi = 0; mi < 4; mi++)
        #pragma unroll
        for (int ni = 0; ni < 4; ni++)
            #pragma unroll
            for (int j = 0; j < 4; j++) acc[mi][ni][j] = 0.f;

    int ntiles = K >> 5;

    // issue stage
    auto issue = [&](int k0, int buf) {
        uint32_t abase = smb + (uint32_t)(buf * STG) * 4;
        #pragma unroll
        for (int i = 0; i < 4; i++)
            cpa16(abase + (uint32_t)((am + 32 * i) * 36 + ak) * 4,
                  A + offA[i] + k0 + ak, szA[i]);
        uint32_t bbase = smb + (uint32_t)(buf * STG + SA_SZ) * 4;
        #pragma unroll
        for (int i = 0; i < 4; i++)
            cpa16(bbase + (uint32_t)((bk + 8 * i) * 136 + bn) * 4,
                  Bm + (size_t)(k0 + bk + 8 * i) * N + n0 + bn, 16);
    };

    issue(0, 0);
    CP_COMMIT();

    for (int it = 0; it < ntiles; it++) {
        if (it + 1 < ntiles) {
            issue((it + 1) << 5, (it + 1) & 1);
            CP_COMMIT();
            CP_WAIT1();
        } else {
            CP_WAIT0();
        }
        __syncthreads();

        const uint32_t* Au = (const uint32_t*)smf + (it & 1) * STG;
        const uint32_t* Bu = Au + SA_SZ;
        #pragma unroll
        for (int kq = 0; kq < 4; kq++) {
            uint32_t af[4][4];
            #pragma unroll
            for (int mi = 0; mi < 4; mi++) {
                const uint32_t* p = Au + (wm * 64 + mi * 16 + lr) * 36 + kq * 8 + lc;
                af[mi][0] = p[0];
                af[mi][1] = p[288];
                af[mi][2] = p[4];
                af[mi][3] = p[292];
            }
            uint32_t bf[4][2];
            #pragma unroll
            for (int ni = 0; ni < 4; ni++) {
                const uint32_t* p = Bu + (kq * 8 + lc) * 136 + wn * 32 + ni * 8 + lr;
                bf[ni][0] = p[0];
                bf[ni][1] = p[544];
            }
            #pragma unroll
            for (int mi = 0; mi < 4; mi++)
                #pragma unroll
                for (int ni = 0; ni < 4; ni++)
                    mma_tf32(acc[mi][ni], af[mi], bf[ni]);
        }
        __syncthreads();
    }

    // epilogue
    #pragma unroll
    for (int mi = 0; mi < 4; mi++) {
        int rb = m0 + wm * 64 + mi * 16 + lr;
        #pragma unroll
        for (int hh = 0; hh < 2; hh++) {
            int r = rb + hh * 8;
            if (r >= M) continue;
            long base = rowmap(r, seg_len, seg_off) * (long)ldc + n0;
            #pragma unroll
            for (int ni = 0; ni < 4; ni++) {
                long p = base + wn * 32 + ni * 8 + lc * 2;
                float v0 = acc[mi][ni][hh * 2 + 0];
                float v1 = acc[mi][ni][hh * 2 + 1];
                if (EPI == 1) { v0 += C[p]; v1 += C[p + 1]; }
                if (EPI == 2) {
                    v0 = tf32r(gelu_tanh(G[p]) * v0);
                    v1 = tf32r(gelu_tanh(G[p + 1]) * v1);
                }
                C[p] = v0; C[p + 1] = v1;
            }
        }
    }
}

// ---------------- host-side helpers ----------------
static void launch_gemm(int epi, const float* A,
                        const float* B0, float* C0,
                        const float* B1, float* C1,
                        const float* G,
                        int M, int N, int K, int lda, int ldc,
                        int seg_len, int seg_off) {
    dim3 grid(N / 128, (M + 127) / 128, B1 ? 2 : 1);
    const float* b1 = B1 ? B1 : B0;
    float* c1 = C1 ? C1 : C0;
    if (epi == 0)
        gemm_tc<0><<<grid, 256, GEMM_SMEM>>>(A, B0, C0, b1, c1, G, M, N, K, lda, ldc, seg_len, seg_off);
    else if (epi == 1)
        gemm_tc<1><<<grid, 256, GEMM_SMEM>>>(A, B0, C0, b1, c1, G, M, N, K, lda, ldc, seg_len, seg_off);
    else
        gemm_tc<2><<<grid, 256, GEMM_SMEM>>>(A, B0, C0, b1, c1, G, M, N, K, lda, ldc, seg_len, seg_off);
}

extern "C" void kernel_launch(void* const* d_in, const int* in_sizes, int n_in,
                              void* d_out, int out_size) {
    const float* prefix = (const float*)d_in[0];
    const float* suffix = (const float*)d_in[1];
    const float* p_ln1  = (const float*)d_in[4];
    const float* p_ln2  = (const float*)d_in[9];
    const float* e_ln1  = (const float*)d_in[13];
    const float* e_ln2  = (const float*)d_in[18];

    // weight arrays (fp32 originals) and their element counts
    const int W_IDX[14] = {5, 6, 7, 8, 10, 11, 12, 14, 15, 16, 17, 19, 20, 21};
    const size_t W_CNT[14] = {
        2ull*DD*DD, 2ull*DD*HD, 2ull*DD*HD, 2ull*DD*DD,
        2ull*DD*MV, 2ull*DD*MV, 2ull*MV*DD,
        2ull*DD*DD, 2ull*DD*HD, 2ull*DD*HD, 2ull*DD*DD,
        2ull*DD*ME, 2ull*DD*ME, 2ull*ME*DD
    };

    float* h = (float*)d_out;
    float *n_, *q_, *k_, *v_, *att_, *mlp_, *wt_;
    cudaGetSymbolAddress((void**)&n_,   g_n);
    cudaGetSymbolAddress((void**)&q_,   g_q);
    cudaGetSymbolAddress((void**)&k_,   g_kb);
    cudaGetSymbolAddress((void**)&v_,   g_vb);
    cudaGetSymbolAddress((void**)&att_, g_att);
    cudaGetSymbolAddress((void**)&mlp_, g_mlp);
    cudaGetSymbolAddress((void**)&wt_,  g_wtf);

    cudaFuncSetAttribute(attn_kernel, cudaFuncAttributeMaxDynamicSharedMemorySize, ATTN_SMEM);
    cudaFuncSetAttribute(gemm_tc<0>, cudaFuncAttributeMaxDynamicSharedMemorySize, GEMM_SMEM);
    cudaFuncSetAttribute(gemm_tc<1>, cudaFuncAttributeMaxDynamicSharedMemorySize, GEMM_SMEM);
    cudaFuncSetAttribute(gemm_tc<2>, cudaFuncAttributeMaxDynamicSharedMemorySize, GEMM_SMEM);

    // round all weights to tf32 once per call
    const float* wt[14];
    {
        size_t off = 0;
        for (int i = 0; i < 14; i++) {
            wt[i] = wt_ + off;
            round_w<<<1024, 256>>>((const float4*)d_in[W_IDX[i]],
                                   (float4*)(wt_ + off), (int)(W_CNT[i] / 4));
            off += W_CNT[i];
        }
    }
    const float *tq_p = wt[0], *tk_p = wt[1], *tv_p = wt[2], *to_p = wt[3];
    const float *tg_p = wt[4], *tu_p = wt[5], *td_p = wt[6];
    const float *tq_e = wt[7], *tk_e = wt[8], *tv_e = wt[9], *to_e = wt[10];
    const float *tg_e = wt[11], *tu_e = wt[12], *td_e = wt[13];

    init_h_kernel<<<NTOK, 256>>>(prefix, suffix, h);

    for (int layer = 0; layer < 2; layer++) {
        size_t lW  = (size_t)layer * DD * DD;
        size_t lKV = (size_t)layer * DD * HD;
        size_t lGp = (size_t)layer * DD * MV;
        size_t lGe = (size_t)layer * DD * ME;

        rmsnorm_kernel<<<NTOK, 256>>>(h, n_, p_ln1 + layer * DD, e_ln1 + layer * DD);

        launch_gemm(0, n_, tq_p + lW, q_, nullptr, nullptr, nullptr,
                    BB*LP, DD, DD, DD, DD, LP, 0);
        launch_gemm(0, n_, tk_p + lKV, k_, tv_p + lKV, v_, nullptr,
                    BB*LP, HD, DD, DD, HD, LP, 0);
        launch_gemm(0, n_, tq_e + lW, q_, nullptr, nullptr, nullptr,
                    BB*LS, DD, DD, DD, DD, LS, LP);
        launch_gemm(0, n_, tk_e + lKV, k_, tv_e + lKV, v_, nullptr,
                    BB*LS, HD, DD, DD, HD, LS, LP);

        rope_kernel<<<NTOK, 256>>>(q_, k_);
        dim3 ag((LTOT + 31) / 32, HH, BB);
        attn_kernel<<<ag, 256, ATTN_SMEM>>>(q_, k_, v_, att_);

        launch_gemm(1, att_, to_p + lW, h, nullptr, nullptr, nullptr,
                    BB*LP, DD, DD, DD, DD, LP, 0);
        launch_gemm(1, att_, to_e + lW, h, nullptr, nullptr, nullptr,
                    BB*LS, DD, DD, DD, DD, LS, LP);

        rmsnorm_kernel<<<NTOK, 256>>>(h, n_, p_ln2 + layer * DD, e_ln2 + layer * DD);

        launch_gemm(0, n_, tg_p + lGp, mlp_, nullptr, nullptr, nullptr,
                    BB*LP, MV, DD, DD, MV, LP, 0);
        launch_gemm(0, n_, tg_e + lGe, mlp_, nullptr, nullptr, nullptr,
                    BB*LS, ME, DD, DD, MV, LS, LP);
        launch_gemm(2, n_, tu_p + lGp, mlp_, nullptr, nullptr, mlp_,
                    BB*LP, MV, DD, DD, MV, LP, 0);
        launch_gemm(2, n_, tu_e + lGe, mlp_, nullptr, nullptr, mlp_,
                    BB*LS, ME, DD, DD, MV, LS, LP);
        launch_gemm(1, mlp_, td_p + lGp, h, nullptr, nullptr, nullptr,
                    BB*LP, DD, MV, MV, DD, LP, 0);
        launch_gemm(1, mlp_, td_e + lGe, h, nullptr, nullptr, nullptr,
                    BB*LS, DD, ME, MV, DD, LS, LP);
    }
}

// round 7
// speedup vs baseline: 4.2689x; 1.5479x over previous
#include <cuda_runtime.h>
#include <math.h>
#include <stdint.h>

// ---------------- problem constants ----------------
#define BB    4
#define LP    768
#define LS    50
#define LTOT  818
#define DD    2048
#define HH    8
#define HD    256
#define MV    8192
#define ME    4096
#define NTOK  (BB*LTOT)
#define SCALE_ 0.0625f

// ---------------- scratch ----------------
__device__ float g_n  [NTOK*DD];
__device__ float g_q  [NTOK*DD];
__device__ float g_kb [NTOK*HD];
__device__ float g_vb [NTOK*HD];
__device__ float g_att[NTOK*DD];
__device__ float g_mlp[(size_t)NTOK*MV];
__device__ float g_wtf[188743680ull];   // tf32-rounded weights

// ---------------- helpers ----------------
__device__ __forceinline__ long rowmap(int r, int seg_len, int seg_off) {
    int b = r / seg_len;
    return (long)b * LTOT + seg_off + (r - b * seg_len);
}
__device__ __forceinline__ float gelu_tanh(float x) {
    float t = tanhf(0.7978845608028654f * (x + 0.044715f * x * x * x));
    return 0.5f * x * (1.0f + t);
}
__device__ __forceinline__ float tf32r(float x) {
    uint32_t u;
    asm("cvt.rna.tf32.f32 %0, %1;" : "=r"(u) : "f"(x));
    return __uint_as_float(u);
}
__device__ __forceinline__ float4 tf32r4(float4 v) {
    v.x = tf32r(v.x); v.y = tf32r(v.y); v.z = tf32r(v.z); v.w = tf32r(v.w);
    return v;
}
__device__ __forceinline__ void cpa16(uint32_t dst, const void* src, int sz) {
    asm volatile("cp.async.ca.shared.global [%0], [%1], 16, %2;\n"
                 :: "r"(dst), "l"(src), "r"(sz));
}
#define CP_COMMIT() asm volatile("cp.async.commit_group;\n")
#define CP_WAIT1()  asm volatile("cp.async.wait_group 1;\n")
#define CP_WAIT0()  asm volatile("cp.async.wait_group 0;\n")

__device__ __forceinline__ void mma_tf32(float* c, const uint32_t* a, const uint32_t* b) {
    asm volatile("mma.sync.aligned.m16n8k8.row.col.f32.tf32.tf32.f32 "
                 "{%0,%1,%2,%3}, {%4,%5,%6,%7}, {%8,%9}, {%0,%1,%2,%3};\n"
                 : "+f"(c[0]), "+f"(c[1]), "+f"(c[2]), "+f"(c[3])
                 : "r"(a[0]), "r"(a[1]), "r"(a[2]), "r"(a[3]),
                   "r"(b[0]), "r"(b[1]));
}

// ---------------- fused weight tf32 rounding (single launch) ----------------
struct RArgs {
    const float4* src[14];
    long cum[15];           // cumulative float4 counts
};
__global__ void round_w_all(RArgs ra, float4* __restrict__ dst) {
    long total = ra.cum[14];
    for (long idx = blockIdx.x * (long)blockDim.x + threadIdx.x; idx < total;
         idx += (long)gridDim.x * blockDim.x) {
        int r = 0;
        while (idx >= ra.cum[r + 1]) ++r;
        float4 v = ra.src[r][idx - ra.cum[r]];
        dst[idx] = tf32r4(v);
    }
}

// ---------------- init: copy prefix/suffix into h (=d_out) ----------------
__global__ void init_h_kernel(const float* __restrict__ prefix,
                              const float* __restrict__ suffix,
                              float* __restrict__ h) {
    int tok = blockIdx.x;
    int b = tok / LTOT, t = tok - b * LTOT;
    const float* src = (t < LP) ? prefix + ((size_t)(b * LP + t)) * DD
                                : suffix + ((size_t)(b * LS + (t - LP))) * DD;
    const float4* s4 = (const float4*)src;
    float4* dst = (float4*)(h + (size_t)tok * DD);
    dst[threadIdx.x]       = s4[threadIdx.x];
    dst[threadIdx.x + 256] = s4[threadIdx.x + 256];
}

// ---------------- rmsnorm (tf32-rounded output: feeds GEMMs) ----------------
__global__ void rmsnorm_kernel(const float* __restrict__ x, float* __restrict__ out,
                               const float* __restrict__ wp, const float* __restrict__ we) {
    int tok = blockIdx.x;
    int t = tok % LTOT;
    const float* w = (t < LP) ? wp : we;
    const float4* xv = (const float4*)(x + (size_t)tok * DD);
    float4 v0 = xv[threadIdx.x];
    float4 v1 = xv[threadIdx.x + 256];
    float ss = v0.x*v0.x + v0.y*v0.y + v0.z*v0.z + v0.w*v0.w
             + v1.x*v1.x + v1.y*v1.y + v1.z*v1.z + v1.w*v1.w;
    __shared__ float red[8];
    #pragma unroll
    for (int o = 16; o; o >>= 1) ss += __shfl_xor_sync(0xffffffffu, ss, o);
    if ((threadIdx.x & 31) == 0) red[threadIdx.x >> 5] = ss;
    __syncthreads();
    float tot = red[0]+red[1]+red[2]+red[3]+red[4]+red[5]+red[6]+red[7];
    float sc = rsqrtf(tot * (1.0f / DD) + 1e-6f);
    const float4* wv = (const float4*)w;
    float4 w0 = wv[threadIdx.x];
    float4 w1 = wv[threadIdx.x + 256];
    float4 o0, o1;
    o0.x = tf32r(v0.x*sc*(1.f+w0.x)); o0.y = tf32r(v0.y*sc*(1.f+w0.y));
    o0.z = tf32r(v0.z*sc*(1.f+w0.z)); o0.w = tf32r(v0.w*sc*(1.f+w0.w));
    o1.x = tf32r(v1.x*sc*(1.f+w1.x)); o1.y = tf32r(v1.y*sc*(1.f+w1.y));
    o1.z = tf32r(v1.z*sc*(1.f+w1.z)); o1.w = tf32r(v1.w*sc*(1.f+w1.w));
    float4* ov = (float4*)(out + (size_t)tok * DD);
    ov[threadIdx.x]       = o0;
    ov[threadIdx.x + 256] = o1;
}

// ---------------- RoPE ----------------
__global__ void rope_kernel(float* __restrict__ q, float* __restrict__ k) {
    int tok = blockIdx.x;
    int pos = tok % LTOT;
    for (int idx = threadIdx.x; idx < 9 * 128; idx += 256) {
        int head = idx >> 7, i = idx & 127;
        float inv = expf(-(float)i * (9.210340371976184f / 128.0f));
        float ang = (float)pos * inv;
        float c = cosf(ang), s = sinf(ang);
        float* base = (head < HH) ? (q + (size_t)tok * DD + head * HD)
                                  : (k + (size_t)tok * HD);
        float x0 = base[i], x1 = base[i + 128];
        base[i]       = x0 * c - x1 * s;
        base[i + 128] = x1 * c + x0 * s;
    }
}

// ---------------- TF32 tensor-core attention ----------------
// 32 queries/block, 256 threads (8 warps: wm=warp>>2 in {0,1}, wn=warp&3).
// Phase1: S = Q@K^T in 13 chunks of 64 keys (mma). Phase2: softmax over 832
// padded cols. Phase3: O = P@V (mma).
#define AQ_LD 260
#define AK_LD 260
#define AV_LD 264
#define ASC_LD 836
#define QS_F (32*AQ_LD)
#define KV_F (64*AV_LD)
#define SC_F (32*ASC_LD)
#define ATTN_SMEM ((QS_F + KV_F + SC_F) * 4)

__global__ void __launch_bounds__(256, 1)
attn_mma(const float* __restrict__ q, const float* __restrict__ k,
         const float* __restrict__ v, float* __restrict__ att) {
    extern __shared__ float sm[];
    float* qs = sm;
    float* kv = sm + QS_F;
    float* sc = kv + KV_F;
    const uint32_t* qsu = (const uint32_t*)qs;
    const uint32_t* kvu = (const uint32_t*)kv;
    const uint32_t* scu = (const uint32_t*)sc;

    int b = blockIdx.z, h = blockIdx.y, qt = blockIdx.x;
    int t = threadIdx.x;
    int q0 = qt * 32;
    int warp = t >> 5, lane = t & 31;
    int wm = warp >> 2, wn = warp & 3;
    int lr = lane >> 2, lc = lane & 3;

    // load Q tile (tf32-rounded)
    for (int i = t; i < 32 * 64; i += 256) {
        int qi = i >> 6, c4 = i & 63;
        int qg = q0 + qi;
        float4 vv = (qg < LTOT)
            ? tf32r4(*(const float4*)(q + ((size_t)(b * LTOT + qg)) * DD + h * HD + c4 * 4))
            : make_float4(0.f, 0.f, 0.f, 0.f);
        *(float4*)(qs + qi * AQ_LD + c4 * 4) = vv;
    }

    // ---- phase 1: scores ----
    for (int kc = 0; kc < 13; kc++) {
        for (int i = t; i < 64 * 64; i += 256) {
            int kj = i >> 6, c4 = i & 63;
            int kg = kc * 64 + kj;
            float4 vv = (kg < LTOT)
                ? tf32r4(*(const float4*)(k + ((size_t)(b * LTOT + kg)) * HD + c4 * 4))
                : make_float4(0.f, 0.f, 0.f, 0.f);
            *(float4*)(kv + kj * AK_LD + c4 * 4) = vv;
        }
        __syncthreads();

        float s0[4] = {0.f, 0.f, 0.f, 0.f};
        float s1[4] = {0.f, 0.f, 0.f, 0.f};
        const uint32_t* qb = qsu + (wm * 16 + lr) * AQ_LD;
        const uint32_t* kb0 = kvu + (wn * 16 + lr) * AK_LD;
        const uint32_t* kb1 = kb0 + 8 * AK_LD;
        #pragma unroll
        for (int kq = 0; kq < 32; kq++) {
            int c = kq * 8 + lc;
            uint32_t a[4] = { qb[c], qb[8 * AQ_LD + c], qb[c + 4], qb[8 * AQ_LD + c + 4] };
            uint32_t b0[2] = { kb0[c], kb0[c + 4] };
            uint32_t b1[2] = { kb1[c], kb1[c + 4] };
            mma_tf32(s0, a, b0);
            mma_tf32(s1, a, b1);
        }
        // epilogue: mask + scale into sc
        int r0 = wm * 16 + lr, r1 = r0 + 8;
        int qg0 = q0 + r0, qg1 = q0 + r1;
        #pragma unroll
        for (int f = 0; f < 2; f++) {
            const float* s = f ? s1 : s0;
            int col = kc * 64 + wn * 16 + f * 8 + 2 * lc;
            #pragma unroll
            for (int cc = 0; cc < 2; cc++) {
                int kg = col + cc;
                bool allow = (kg < LP);
                sc[r0 * ASC_LD + kg] = (allow || kg <= qg0) ? s[cc]     * SCALE_ : -1e30f;
                sc[r1 * ASC_LD + kg] = (allow || kg <= qg1) ? s[cc + 2] * SCALE_ : -1e30f;
            }
        }
        __syncthreads();
    }

    // ---- phase 2: softmax over 832 cols (padded cols are -1e30 -> 0) ----
    {
        for (int j = 0; j < 4; j++) {
            float* row = sc + (warp * 4 + j) * ASC_LD;
            float mx = -1e30f;
            #pragma unroll 4
            for (int kk = lane; kk < 832; kk += 32) mx = fmaxf(mx, row[kk]);
            #pragma unroll
            for (int o = 16; o; o >>= 1) mx = fmaxf(mx, __shfl_xor_sync(0xffffffffu, mx, o));
            float sum = 0.f;
            #pragma unroll 4
            for (int kk = lane; kk < 832; kk += 32) {
                float e = expf(row[kk] - mx);
                row[kk] = e;
                sum += e;
            }
            #pragma unroll
            for (int o = 16; o; o >>= 1) sum += __shfl_xor_sync(0xffffffffu, sum, o);
            float invs = 1.0f / sum;
            #pragma unroll 4
            for (int kk = lane; kk < 832; kk += 32) row[kk] = tf32r(row[kk] * invs);
        }
    }
    __syncthreads();

    // ---- phase 3: O = P @ V ----
    float o[8][4];
    #pragma unroll
    for (int ni = 0; ni < 8; ni++)
        #pragma unroll
        for (int j = 0; j < 4; j++) o[ni][j] = 0.f;

    for (int kc = 0; kc < 13; kc++) {
        for (int i = t; i < 64 * 64; i += 256) {
            int kj = i >> 6, c4 = i & 63;
            int kg = kc * 64 + kj;
            float4 vv = (kg < LTOT)
                ? tf32r4(*(const float4*)(v + ((size_t)(b * LTOT + kg)) * HD + c4 * 4))
                : make_float4(0.f, 0.f, 0.f, 0.f);
            *(float4*)(kv + kj * AV_LD + c4 * 4) = vv;
        }
        __syncthreads();

        const uint32_t* pb = scu + (wm * 16 + lr) * ASC_LD + kc * 64;
        #pragma unroll
        for (int kq = 0; kq < 8; kq++) {
            int c = kq * 8 + lc;
            uint32_t a[4] = { pb[c], pb[8 * ASC_LD + c], pb[c + 4], pb[8 * ASC_LD + c + 4] };
            const uint32_t* vb0 = kvu + (kq * 8 + lc) * AV_LD + wn * 64 + lr;
            const uint32_t* vb1 = vb0 + 4 * AV_LD;
            #pragma unroll
            for (int ni = 0; ni < 8; ni++) {
                uint32_t bfr[2] = { vb0[ni * 8], vb1[ni * 8] };
                mma_tf32(o[ni], a, bfr);
            }
        }
        __syncthreads();
    }

    // store O (tf32-rounded: feeds o-proj GEMM)
    int r0 = wm * 16 + lr, r1 = r0 + 8;
    int qg0 = q0 + r0, qg1 = q0 + r1;
    #pragma unroll
    for (int ni = 0; ni < 8; ni++) {
        int d = h * HD + wn * 64 + ni * 8 + 2 * lc;
        if (qg0 < LTOT) {
            float* dst = att + ((size_t)(b * LTOT + qg0)) * DD + d;
            dst[0] = tf32r(o[ni][0]); dst[1] = tf32r(o[ni][1]);
        }
        if (qg1 < LTOT) {
            float* dst = att + ((size_t)(b * LTOT + qg1)) * DD + d;
            dst[0] = tf32r(o[ni][2]); dst[1] = tf32r(o[ni][3]);
        }
    }
}

// ---------------- TF32 tensor-core GEMM (multi-problem via blockIdx.z) ----------------
#define SA_SZ (128*36)
#define SB_SZ (32*136)
#define STG   (SA_SZ + SB_SZ)
#define GEMM_SMEM (2*STG*4)

struct GArgs {
    const float* A;
    const float* B[4];
    float*       C[4];
    const float* G[4];
    int M[4], N[4], K[4], ldc[4], seg_len[4], seg_off[4];
    int lda;
};

template <int EPI>
__global__ void __launch_bounds__(256, 2)
gemm_tc(GArgs ga) {
    int z = blockIdx.z;
    int M = ga.M[z], N = ga.N[z], K = ga.K[z];
    int ldc = ga.ldc[z], seg_len = ga.seg_len[z], seg_off = ga.seg_off[z];
    int lda = ga.lda;
    int m0 = blockIdx.y * 128, n0 = blockIdx.x * 128;
    if (m0 >= M || n0 >= N) return;
    const float* A  = ga.A;
    const float* Bm = ga.B[z];
    float* C        = ga.C[z];
    const float* G  = ga.G[z];

    extern __shared__ float smf[];
    int t = threadIdx.x;
    uint32_t smb = (uint32_t)__cvta_generic_to_shared(smf);

    int am = t >> 3;
    int ak = (t & 7) * 4;
    int bk = t >> 5;
    int bn = (t & 31) * 4;
    long offA[4]; int szA[4];
    #pragma unroll
    for (int i = 0; i < 4; i++) {
        int r = m0 + am + 32 * i;
        bool vld = r < M;
        offA[i] = vld ? rowmap(r, seg_len, seg_off) * (long)lda : 0;
        szA[i] = vld ? 16 : 0;
    }

    int warp = t >> 5, lane = t & 31;
    int wm = warp >> 2, wn = warp & 3;
    int lr = lane >> 2, lc = lane & 3;

    float acc[4][4][4];
    #pragma unroll
    for (int mi = 0; mi < 4; mi++)
        #pragma unroll
        for (int ni = 0; ni < 4; ni++)
            #pragma unroll
            for (int j = 0; j < 4; j++) acc[mi][ni][j] = 0.f;

    int ntiles = K >> 5;

    auto issue = [&](int k0, int buf) {
        uint32_t abase = smb + (uint32_t)(buf * STG) * 4;
        #pragma unroll
        for (int i = 0; i < 4; i++)
            cpa16(abase + (uint32_t)((am + 32 * i) * 36 + ak) * 4,
                  A + offA[i] + k0 + ak, szA[i]);
        uint32_t bbase = smb + (uint32_t)(buf * STG + SA_SZ) * 4;
        #pragma unroll
        for (int i = 0; i < 4; i++)
            cpa16(bbase + (uint32_t)((bk + 8 * i) * 136 + bn) * 4,
                  Bm + (size_t)(k0 + bk + 8 * i) * N + n0 + bn, 16);
    };

    issue(0, 0);
    CP_COMMIT();

    for (int it = 0; it < ntiles; it++) {
        if (it + 1 < ntiles) {
            issue((it + 1) << 5, (it + 1) & 1);
            CP_COMMIT();
            CP_WAIT1();
        } else {
            CP_WAIT0();
        }
        __syncthreads();

        const uint32_t* Au = (const uint32_t*)smf + (it & 1) * STG;
        const uint32_t* Bu = Au + SA_SZ;
        #pragma unroll
        for (int kq = 0; kq < 4; kq++) {
            uint32_t af[4][4];
            #pragma unroll
            for (int mi = 0; mi < 4; mi++) {
                const uint32_t* p = Au + (wm * 64 + mi * 16 + lr) * 36 + kq * 8 + lc;
                af[mi][0] = p[0];
                af[mi][1] = p[288];
                af[mi][2] = p[4];
                af[mi][3] = p[292];
            }
            uint32_t bf[4][2];
            #pragma unroll
            for (int ni = 0; ni < 4; ni++) {
                const uint32_t* p = Bu + (kq * 8 + lc) * 136 + wn * 32 + ni * 8 + lr;
                bf[ni][0] = p[0];
                bf[ni][1] = p[544];
            }
            #pragma unroll
            for (int mi = 0; mi < 4; mi++)
                #pragma unroll
                for (int ni = 0; ni < 4; ni++)
                    mma_tf32(acc[mi][ni], af[mi], bf[ni]);
        }
        __syncthreads();
    }

    #pragma unroll
    for (int mi = 0; mi < 4; mi++) {
        int rb = m0 + wm * 64 + mi * 16 + lr;
        #pragma unroll
        for (int hh = 0; hh < 2; hh++) {
            int r = rb + hh * 8;
            if (r >= M) continue;
            long base = rowmap(r, seg_len, seg_off) * (long)ldc + n0;
            #pragma unroll
            for (int ni = 0; ni < 4; ni++) {
                long p = base + wn * 32 + ni * 8 + lc * 2;
                float v0 = acc[mi][ni][hh * 2 + 0];
                float v1 = acc[mi][ni][hh * 2 + 1];
                if (EPI == 1) { v0 += C[p]; v1 += C[p + 1]; }
                if (EPI == 2) {
                    v0 = tf32r(gelu_tanh(G[p]) * v0);
                    v1 = tf32r(gelu_tanh(G[p + 1]) * v1);
                }
                C[p] = v0; C[p + 1] = v1;
            }
        }
    }
}

// ---------------- host-side launch helper ----------------
struct SubProb {
    const float* B; float* C; const float* G;
    int M, N, K, ldc, seg_len, seg_off;
};

static void launch_gemm_multi(int epi, const float* A, int lda,
                              const SubProb* sp, int nz) {
    GArgs ga;
    ga.A = A; ga.lda = lda;
    int maxN = 0, maxM = 0;
    for (int z = 0; z < nz; z++) {
        ga.B[z] = sp[z].B; ga.C[z] = sp[z].C; ga.G[z] = sp[z].G;
        ga.M[z] = sp[z].M; ga.N[z] = sp[z].N; ga.K[z] = sp[z].K;
        ga.ldc[z] = sp[z].ldc; ga.seg_len[z] = sp[z].seg_len; ga.seg_off[z] = sp[z].seg_off;
        if (sp[z].N > maxN) maxN = sp[z].N;
        if (sp[z].M > maxM) maxM = sp[z].M;
    }
    for (int z = nz; z < 4; z++) ga = ga; // no-op
    dim3 grid(maxN / 128, (maxM + 127) / 128, nz);
    if (epi == 0)      gemm_tc<0><<<grid, 256, GEMM_SMEM>>>(ga);
    else if (epi == 1) gemm_tc<1><<<grid, 256, GEMM_SMEM>>>(ga);
    else               gemm_tc<2><<<grid, 256, GEMM_SMEM>>>(ga);
}

extern "C" void kernel_launch(void* const* d_in, const int* in_sizes, int n_in,
                              void* d_out, int out_size) {
    const float* prefix = (const float*)d_in[0];
    const float* suffix = (const float*)d_in[1];
    const float* p_ln1  = (const float*)d_in[4];
    const float* p_ln2  = (const float*)d_in[9];
    const float* e_ln1  = (const float*)d_in[13];
    const float* e_ln2  = (const float*)d_in[18];

    const int W_IDX[14] = {5, 6, 7, 8, 10, 11, 12, 14, 15, 16, 17, 19, 20, 21};
    const size_t W_CNT[14] = {
        2ull*DD*DD, 2ull*DD*HD, 2ull*DD*HD, 2ull*DD*DD,
        2ull*DD*MV, 2ull*DD*MV, 2ull*MV*DD,
        2ull*DD*DD, 2ull*DD*HD, 2ull*DD*HD, 2ull*DD*DD,
        2ull*DD*ME, 2ull*DD*ME, 2ull*ME*DD
    };

    float* h = (float*)d_out;
    float *n_, *q_, *k_, *v_, *att_, *mlp_, *wt_;
    cudaGetSymbolAddress((void**)&n_,   g_n);
    cudaGetSymbolAddress((void**)&q_,   g_q);
    cudaGetSymbolAddress((void**)&k_,   g_kb);
    cudaGetSymbolAddress((void**)&v_,   g_vb);
    cudaGetSymbolAddress((void**)&att_, g_att);
    cudaGetSymbolAddress((void**)&mlp_, g_mlp);
    cudaGetSymbolAddress((void**)&wt_,  g_wtf);

    cudaFuncSetAttribute(attn_mma, cudaFuncAttributeMaxDynamicSharedMemorySize, ATTN_SMEM);
    cudaFuncSetAttribute(gemm_tc<0>, cudaFuncAttributeMaxDynamicSharedMemorySize, GEMM_SMEM);
    cudaFuncSetAttribute(gemm_tc<1>, cudaFuncAttributeMaxDynamicSharedMemorySize, GEMM_SMEM);
    cudaFuncSetAttribute(gemm_tc<2>, cudaFuncAttributeMaxDynamicSharedMemorySize, GEMM_SMEM);

    // round all weights to tf32 (single fused launch)
    const float* wt[14];
    {
        RArgs ra;
        long cum = 0;
        for (int i = 0; i < 14; i++) {
            ra.src[i] = (const float4*)d_in[W_IDX[i]];
            ra.cum[i] = cum;
            wt[i] = wt_ + cum * 4;
            cum += (long)(W_CNT[i] / 4);
        }
        ra.cum[14] = cum;
        round_w_all<<<4096, 256>>>(ra, (float4*)wt_);
    }
    const float *tq_p = wt[0], *tk_p = wt[1], *tv_p = wt[2], *to_p = wt[3];
    const float *tg_p = wt[4], *tu_p = wt[5], *td_p = wt[6];
    const float *tq_e = wt[7], *tk_e = wt[8], *tv_e = wt[9], *to_e = wt[10];
    const float *tg_e = wt[11], *tu_e = wt[12], *td_e = wt[13];

    init_h_kernel<<<NTOK, 256>>>(prefix, suffix, h);

    for (int layer = 0; layer < 2; layer++) {
        size_t lW  = (size_t)layer * DD * DD;
        size_t lKV = (size_t)layer * DD * HD;
        size_t lGp = (size_t)layer * DD * MV;
        size_t lGe = (size_t)layer * DD * ME;

        rmsnorm_kernel<<<NTOK, 256>>>(h, n_, p_ln1 + layer * DD, e_ln1 + layer * DD);

        {   // q projection (prefix + suffix)
            SubProb sp[2] = {
                { tq_p + lW, q_, nullptr, BB*LP, DD, DD, DD, LP, 0 },
                { tq_e + lW, q_, nullptr, BB*LS, DD, DD, DD, LS, LP } };
            launch_gemm_multi(0, n_, DD, sp, 2);
        }
        {   // k/v projections (4-way)
            SubProb sp[4] = {
                { tk_p + lKV, k_, nullptr, BB*LP, HD, DD, HD, LP, 0 },
                { tv_p + lKV, v_, nullptr, BB*LP, HD, DD, HD, LP, 0 },
                { tk_e + lKV, k_, nullptr, BB*LS, HD, DD, HD, LS, LP },
                { tv_e + lKV, v_, nullptr, BB*LS, HD, DD, HD, LS, LP } };
            launch_gemm_multi(0, n_, DD, sp, 4);
        }

        rope_kernel<<<NTOK, 256>>>(q_, k_);
        dim3 ag(26, HH, BB);
        attn_mma<<<ag, 256, ATTN_SMEM>>>(q_, k_, v_, att_);

        {   // o projection + residual
            SubProb sp[2] = {
                { to_p + lW, h, nullptr, BB*LP, DD, DD, DD, LP, 0 },
                { to_e + lW, h, nullptr, BB*LS, DD, DD, DD, LS, LP } };
            launch_gemm_multi(1, att_, DD, sp, 2);
        }

        rmsnorm_kernel<<<NTOK, 256>>>(h, n_, p_ln2 + layer * DD, e_ln2 + layer * DD);

        {   // gate
            SubProb sp[2] = {
                { tg_p + lGp, mlp_, nullptr, BB*LP, MV, DD, MV, LP, 0 },
                { tg_e + lGe, mlp_, nullptr, BB*LS, ME, DD, MV, LS, LP } };
            launch_gemm_multi(0, n_, DD, sp, 2);
        }
        {   // up (fused gelu(gate)*up)
            SubProb sp[2] = {
                { tu_p + lGp, mlp_, mlp_, BB*LP, MV, DD, MV, LP, 0 },
                { tu_e + lGe, mlp_, mlp_, BB*LS, ME, DD, MV, LS, LP } };
            launch_gemm_multi(2, n_, DD, sp, 2);
        }
        {   // down + residual
            SubProb sp[2] = {
                { td_p + lGp, h, nullptr, BB*LP, DD, MV, DD, LP, 0 },
                { td_e + lGe, h, nullptr, BB*LS, DD, ME, DD, LS, LP } };
            launch_gemm_multi(1, mlp_, MV, sp, 2);
        }
    }
}